// round 1
// baseline (speedup 1.0000x reference)
#include <cuda_runtime.h>
#include <float.h>

#define PH 7
#define PW 7
#define BD 2
#define ND 96
#define HD 64
#define WD 64
#define CD 128

__global__ void __launch_bounds__(128, 8)
roipool_kernel(const float* __restrict__ fmap,
               const float* __restrict__ rois,
               float* __restrict__ out) {
    const int bin = blockIdx.x;               // ((b*N+n)*PH+ph)*PW+pw
    const int pw  = bin % PW;
    const int ph  = (bin / PW) % PH;
    const int roi = bin / (PH * PW);          // b*N+n
    const int b   = roi / ND;

    // roi = [x_center, y_center, width, height]
    const float xc = rois[roi * 4 + 0];
    const float yc = rois[roi * 4 + 1];
    const float ww = rois[roi * 4 + 2];
    const float hh = rois[roi * 4 + 3];

    // rows (y axis uses yc, hh)
    const float halfh = floorf(hh * 0.5f);
    const int ys   = (int)(yc - halfh);
    const int ye   = (int)(yc + halfh);
    const int lenh = ye - ys;
    const int sth  = max(lenh / PH, 1);
    const int ry0  = ph * sth;
    const int ry1  = (ph == PH - 1) ? lenh : ry0 + sth;
    const int y0   = max(ys + ry0, 0);
    const int y1   = min(ys + ry1, HD);

    // cols (x axis uses xc, ww)
    const float halfw = floorf(ww * 0.5f);
    const int xs   = (int)(xc - halfw);
    const int xe   = (int)(xc + halfw);
    const int lenw = xe - xs;
    const int stw  = max(lenw / PW, 1);
    const int rx0  = pw * stw;
    const int rx1  = (pw == PW - 1) ? lenw : rx0 + stw;
    const int x0   = max(xs + rx0, 0);
    const int x1   = min(xs + rx1, WD);

    const int lane = threadIdx.x & 31;
    const int warp = threadIdx.x >> 5;

    const int nx   = x1 - x0;
    const int npix = (y1 - y0) * nx;

    float4 acc = make_float4(-FLT_MAX, -FLT_MAX, -FLT_MAX, -FLT_MAX);

    // each warp strides the flat pixel list; lane = 4-channel group
    const float4* base = (const float4*)(fmap + ((size_t)b * HD) * WD * CD) + lane;
    for (int p = warp; p < npix; p += 4) {
        const int y = y0 + p / nx;
        const int x = x0 + p % nx;
        float4 v = __ldg(base + (y * WD + x) * (CD / 4));
        acc.x = fmaxf(acc.x, v.x);
        acc.y = fmaxf(acc.y, v.y);
        acc.z = fmaxf(acc.z, v.z);
        acc.w = fmaxf(acc.w, v.w);
    }

    __shared__ float4 smax[4][32];
    smax[warp][lane] = acc;
    __syncthreads();

    if (warp == 0) {
        float4 a = smax[0][lane];
        #pragma unroll
        for (int w = 1; w < 4; w++) {
            float4 c = smax[w][lane];
            a.x = fmaxf(a.x, c.x);
            a.y = fmaxf(a.y, c.y);
            a.z = fmaxf(a.z, c.z);
            a.w = fmaxf(a.w, c.w);
        }
        ((float4*)out)[(size_t)bin * 32 + lane] = a;
    }
}

extern "C" void kernel_launch(void* const* d_in, const int* in_sizes, int n_in,
                              void* d_out, int out_size) {
    const float* fmap = (const float*)d_in[0];
    const float* rois = (const float*)d_in[1];
    float* out = (float*)d_out;
    const int nbins = BD * ND * PH * PW;   // 9408
    roipool_kernel<<<nbins, 128>>>(fmap, rois, out);
}

// round 3
// speedup vs baseline: 1.0582x; 1.0582x over previous
#include <cuda_runtime.h>
#include <float.h>

#define PH 7
#define PW 7
#define BD 2
#define ND 96
#define HD 64
#define WD 64
#define CD 128

#define WARPS_PER_CTA 8
#define NBINS (BD * ND * PH * PW)   // 9408

__global__ void __launch_bounds__(32 * WARPS_PER_CTA, 4)
roipool_kernel(const float* __restrict__ fmap,
               const float* __restrict__ rois,
               float* __restrict__ out) {
    const int warp = threadIdx.x >> 5;
    const int lane = threadIdx.x & 31;
    const int bin  = blockIdx.x * WARPS_PER_CTA + warp;   // ((b*N+n)*PH+ph)*PW+pw
    if (bin >= NBINS) return;

    const int pw  = bin % PW;
    const int ph  = (bin / PW) % PH;
    const int roi = bin / (PH * PW);          // b*N+n
    const int b   = roi / ND;

    // roi = [x_center, y_center, width, height]
    const float4 r4 = __ldg((const float4*)(rois) + roi);
    const float xc = r4.x, yc = r4.y, ww = r4.z, hh = r4.w;

    // rows (y axis uses yc, hh)
    const float halfh = floorf(hh * 0.5f);
    const int ys   = (int)(yc - halfh);
    const int ye   = (int)(yc + halfh);
    const int lenh = ye - ys;
    const int sth  = max(lenh / PH, 1);
    const int ry0  = ph * sth;
    const int ry1  = (ph == PH - 1) ? lenh : ry0 + sth;
    const int y0   = max(ys + ry0, 0);
    const int y1   = min(ys + ry1, HD);

    // cols (x axis uses xc, ww)
    const float halfw = floorf(ww * 0.5f);
    const int xs   = (int)(xc - halfw);
    const int xe   = (int)(xc + halfw);
    const int lenw = xe - xs;
    const int stw  = max(lenw / PW, 1);
    const int rx0  = pw * stw;
    const int rx1  = (pw == PW - 1) ? lenw : rx0 + stw;
    const int x0   = max(xs + rx0, 0);
    const int x1   = min(xs + rx1, WD);

    const int nx = x1 - x0;

    float4 acc = make_float4(-FLT_MAX, -FLT_MAX, -FLT_MAX, -FLT_MAX);

    // lane = 4-channel group; one LDG.128 x 32 lanes = one full pixel (512B)
    const float4* base = (const float4*)(fmap + ((size_t)b * HD) * WD * CD)
                         + lane;
    for (int y = y0; y < y1; ++y) {
        const float4* row = base + (y * WD + x0) * (CD / 4);
        #pragma unroll 4
        for (int x = 0; x < nx; ++x) {
            float4 v = __ldg(row + x * (CD / 4));
            acc.x = fmaxf(acc.x, v.x);
            acc.y = fmaxf(acc.y, v.y);
            acc.z = fmaxf(acc.z, v.z);
            acc.w = fmaxf(acc.w, v.w);
        }
    }

    ((float4*)out)[(size_t)bin * 32 + lane] = acc;
}

extern "C" void kernel_launch(void* const* d_in, const int* in_sizes, int n_in,
                              void* d_out, int out_size) {
    const float* fmap = (const float*)d_in[0];
    const float* rois = (const float*)d_in[1];
    float* out = (float*)d_out;
    const int grid = (NBINS + WARPS_PER_CTA - 1) / WARPS_PER_CTA;
    roipool_kernel<<<grid, 32 * WARPS_PER_CTA>>>(fmap, rois, out);
}

// round 5
// speedup vs baseline: 1.2655x; 1.1959x over previous
#include <cuda_runtime.h>
#include <float.h>

#define PH 7
#define PW 7
#define BD 2
#define ND 96
#define HD 64
#define WD 64
#define CD 128

#define WARPS_PER_CTA 8
#define NBINS (BD * ND * PH * PW)   // 9408
#define UN 8                        // prefetch depth (MLP)

__device__ __forceinline__ void fmax4(float4& a, const float4& v) {
    a.x = fmaxf(a.x, v.x);
    a.y = fmaxf(a.y, v.y);
    a.z = fmaxf(a.z, v.z);
    a.w = fmaxf(a.w, v.w);
}

__global__ void __launch_bounds__(32 * WARPS_PER_CTA)
roipool_kernel(const float* __restrict__ fmap,
               const float* __restrict__ rois,
               float* __restrict__ out) {
    const int warp = threadIdx.x >> 5;
    const int lane = threadIdx.x & 31;
    const int bin  = blockIdx.x * WARPS_PER_CTA + warp;   // ((b*N+n)*PH+ph)*PW+pw
    if (bin >= NBINS) return;

    const int pw  = bin % PW;
    const int ph  = (bin / PW) % PH;
    const int roi = bin / (PH * PW);          // b*N+n
    const int b   = roi / ND;

    // roi = [x_center, y_center, width, height]
    const float4 r4 = __ldg((const float4*)(rois) + roi);
    const float xc = r4.x, yc = r4.y, ww = r4.z, hh = r4.w;

    // rows (y axis: yc, hh)
    const float halfh = floorf(hh * 0.5f);
    const int ys   = (int)(yc - halfh);
    const int ye   = (int)(yc + halfh);
    const int lenh = ye - ys;
    const int sth  = max(lenh / PH, 1);
    const int ry0  = ph * sth;
    const int ry1  = (ph == PH - 1) ? lenh : ry0 + sth;
    const int y0   = max(ys + ry0, 0);
    const int y1   = min(ys + ry1, HD);

    // cols (x axis: xc, ww)
    const float halfw = floorf(ww * 0.5f);
    const int xs   = (int)(xc - halfw);
    const int xe   = (int)(xc + halfw);
    const int lenw = xe - xs;
    const int stw  = max(lenw / PW, 1);
    const int rx0  = pw * stw;
    const int rx1  = (pw == PW - 1) ? lenw : rx0 + stw;
    const int x0   = max(xs + rx0, 0);
    const int x1   = min(xs + rx1, WD);

    const int nx   = x1 - x0;
    const int npix = (y1 - y0) * nx;

    float4 acc = make_float4(-FLT_MAX, -FLT_MAX, -FLT_MAX, -FLT_MAX);

    // lane = 4-channel group; incremental pointer walk over the bin rect,
    // software-pipelined to keep UN loads in flight (data lives in L2).
    const float4* p = (const float4*)(fmap + ((size_t)b * HD) * WD * CD)
                      + (y0 * WD + x0) * (CD / 4) + lane;
    const int rowskip = (WD - nx) * (CD / 4);
    int xi = 0;

#define ADV { p += (CD / 4); if (++xi == nx) { xi = 0; p += rowskip; } }

    float4 buf[UN];
    int i = 0;
    for (; i + UN <= npix; i += UN) {
        #pragma unroll
        for (int k = 0; k < UN; k++) { buf[k] = __ldg(p); ADV }
        #pragma unroll
        for (int k = 0; k < UN; k++) fmax4(acc, buf[k]);
    }
    for (; i < npix; i++) {
        float4 v = __ldg(p); ADV
        fmax4(acc, v);
    }

    ((float4*)out)[(size_t)bin * 32 + lane] = acc;
}

extern "C" void kernel_launch(void* const* d_in, const int* in_sizes, int n_in,
                              void* d_out, int out_size) {
    const float* fmap = (const float*)d_in[0];
    const float* rois = (const float*)d_in[1];
    float* out = (float*)d_out;
    const int grid = (NBINS + WARPS_PER_CTA - 1) / WARPS_PER_CTA;
    roipool_kernel<<<grid, 32 * WARPS_PER_CTA>>>(fmap, rois, out);
}